// round 5
// baseline (speedup 1.0000x reference)
#include <cuda_runtime.h>

#define IMG_H 512
#define IMG_W 512
#define TILE_ROWS 32        // output rows per block
#define TILE_COLS 128       // output cols per block
#define SROW 132            // floats per smem row: [0..127] interior, [128] left halo, [129] right halo, pad to 132

__global__ __launch_bounds__(256)
void cheby_smooth_kernel(const float* __restrict__ x,
                         const float* __restrict__ f,
                         const float* __restrict__ kA,
                         float* __restrict__ out)
{
    __shared__ float k[9];
    __shared__ __align__(16) float sx[TILE_ROWS + 2][SROW];

    const int b     = blockIdx.z;
    const int lane  = threadIdx.x;              // 0..31
    const int wy    = threadIdx.y;              // 0..7 (warp id in block)
    const int tid   = wy * 32 + lane;
    const int r_top = blockIdx.y * TILE_ROWS;   // first output row of this block
    const int cbase = blockIdx.x * TILE_COLS;   // first output col of this block

    if (tid < 9) k[tid] = kA[b * 9 + tid];

    const size_t base = (size_t)b * IMG_H * IMG_W;
    const float* __restrict__ xb = x + base;
    const float* __restrict__ fb = f + base;
    float* __restrict__ ob = out + base;

    // ---- Phase 1: cooperative load of x tile (rows r_top-1 .. r_top+32) into smem ----
    // Warp wy loads smem rows wy, wy+8, wy+16, wy+24, wy+32 (34 rows total).
    #pragma unroll
    for (int it = 0; it < 5; ++it) {
        const int i = it * 8 + wy;
        if (i < TILE_ROWS + 2) {
            const int gr = r_top - 1 + i;
            const bool vr = (gr >= 0) && (gr < IMG_H);
            const float* __restrict__ row = xb + (size_t)gr * IMG_W;
            const float4 v = vr ? *reinterpret_cast<const float4*>(row + cbase + 4 * lane)
                                : make_float4(0.f, 0.f, 0.f, 0.f);
            *reinterpret_cast<float4*>(&sx[i][4 * lane]) = v;
            if (lane == 0)
                sx[i][128] = (vr && cbase > 0)                  ? row[cbase - 1]   : 0.f;
            if (lane == 1)
                sx[i][129] = (vr && cbase + TILE_COLS < IMG_W)  ? row[cbase + 128] : 0.f;
        }
    }
    __syncthreads();

    // ---- Phase 2: compute 4 output rows per thread from smem ----
    const float inv6 = 1.0f / 6.0f;
    const int c0 = 4 * lane;

    #pragma unroll
    for (int j = 0; j < 4; ++j) {
        const int orow = wy * 4 + j;                 // 0..31 within tile
        float a0 = 0.f, a1 = 0.f, a2 = 0.f, a3 = 0.f;
        float4 xc = make_float4(0.f, 0.f, 0.f, 0.f);

        #pragma unroll
        for (int t = 0; t < 3; ++t) {
            const float* __restrict__ s = sx[orow + t];   // smem row for x-row (r_top+orow-1+t)
            const float4 m = *reinterpret_cast<const float4*>(&s[c0]);
            const float  l = (c0 == 0)                 ? s[128] : s[c0 - 1];
            const float  r = (c0 == TILE_COLS - 4)     ? s[129] : s[c0 + 4];
            if (t == 1) xc = m;
            const float k0 = k[t * 3 + 0];
            const float k1 = k[t * 3 + 1];
            const float k2 = k[t * 3 + 2];
            a0 = fmaf(l,   k0, fmaf(m.x, k1, fmaf(m.y, k2, a0)));
            a1 = fmaf(m.x, k0, fmaf(m.y, k1, fmaf(m.z, k2, a1)));
            a2 = fmaf(m.y, k0, fmaf(m.z, k1, fmaf(m.w, k2, a2)));
            a3 = fmaf(m.z, k0, fmaf(m.w, k1, fmaf(r,   k2, a3)));
        }

        const size_t goff = (size_t)(r_top + orow) * IMG_W + cbase + c0;
        const float4 fv = *reinterpret_cast<const float4*>(fb + goff);

        float4 o;
        o.x = xc.x + (fv.x - a0) * inv6;
        o.y = xc.y + (fv.y - a1) * inv6;
        o.z = xc.z + (fv.z - a2) * inv6;
        o.w = xc.w + (fv.w - a3) * inv6;
        *reinterpret_cast<float4*>(ob + goff) = o;
    }
}

extern "C" void kernel_launch(void* const* d_in, const int* in_sizes, int n_in,
                              void* d_out, int out_size)
{
    const float* x  = (const float*)d_in[0];   // [64,1,512,512]
    const float* f  = (const float*)d_in[1];   // [64,1,512,512]
    const float* kA = (const float*)d_in[2];   // [64,1,3,3]
    float* out = (float*)d_out;

    dim3 block(32, 8, 1);
    dim3 grid(IMG_W / TILE_COLS, IMG_H / TILE_ROWS, 64); // (4, 16, 64)
    cheby_smooth_kernel<<<grid, block>>>(x, f, kA, out);
}

// round 6
// speedup vs baseline: 1.3961x; 1.3961x over previous
#include <cuda_runtime.h>

#define IMG_H 512
#define IMG_W 512

__global__ __launch_bounds__(128)
void cheby_smooth_kernel(const float* __restrict__ x,
                         const float* __restrict__ f,
                         const float* __restrict__ kA,
                         float* __restrict__ out)
{
    const int b    = blockIdx.z;
    const int lane = threadIdx.x;                                 // blockDim.x == 32
    const int r0   = (blockIdx.y * 4 + threadIdx.y) * 8;          // first of 8 output rows
    const int c0   = (blockIdx.x * 32 + lane) * 4;                // first of 4 output cols

    __shared__ float k[9];
    if (threadIdx.y == 0 && lane < 9)
        k[lane] = kA[b * 9 + lane];
    __syncthreads();

    const size_t base = (size_t)b * IMG_H * IMG_W;
    const float* __restrict__ xb = x + base;
    const float* __restrict__ fb = f + base;
    float* __restrict__ ob = out + base;

    const float inv6 = 1.0f / 6.0f;

    // Double-buffered chunk state: each chunk = 2 output rows, needs 4 x-rows + 2 f-rows.
    float4 mid[2][4];
    float  bl[2][4], br[2][4];   // boundary scalars (lanes 0/31 only carry real data)
    float4 fv[2][2];

    // ---- chunk loader: issue all global loads for chunk c into buffer buf ----
    #define LOAD_CHUNK(c, buf)                                                        \
    {                                                                                 \
        _Pragma("unroll")                                                             \
        for (int i = 0; i < 4; ++i) {                                                 \
            const int gr = r0 + 2 * (c) - 1 + i;                                      \
            const bool valid = (gr >= 0) && (gr < IMG_H);                             \
            const float* __restrict__ row = xb + (size_t)gr * IMG_W;                  \
            mid[buf][i] = valid ? *reinterpret_cast<const float4*>(row + c0)          \
                                : make_float4(0.f, 0.f, 0.f, 0.f);                    \
            bl[buf][i] = (lane == 0  && valid && c0 > 0)         ? row[c0 - 1] : 0.f; \
            br[buf][i] = (lane == 31 && valid && c0 + 4 < IMG_W) ? row[c0 + 4] : 0.f; \
        }                                                                             \
        fv[buf][0] = *reinterpret_cast<const float4*>(fb + (size_t)(r0 + 2*(c)    ) * IMG_W + c0); \
        fv[buf][1] = *reinterpret_cast<const float4*>(fb + (size_t)(r0 + 2*(c) + 1) * IMG_W + c0); \
    }

    // Prologue: load chunk 0.
    LOAD_CHUNK(0, 0)

    #pragma unroll
    for (int c = 0; c < 4; ++c) {
        const int cur = c & 1;
        const int nxt = cur ^ 1;

        // Issue next chunk's loads BEFORE consuming the current one.
        if (c < 3)
            LOAD_CHUNK(c + 1, nxt)

        // Halo exchange for the current chunk (4 x-rows).
        float lf[4], rt[4];
        #pragma unroll
        for (int i = 0; i < 4; ++i) {
            const float l = __shfl_up_sync(0xffffffffu, mid[cur][i].w, 1);
            const float r = __shfl_down_sync(0xffffffffu, mid[cur][i].x, 1);
            lf[i] = (lane == 0)  ? bl[cur][i] : l;
            rt[i] = (lane == 31) ? br[cur][i] : r;
        }

        // Compute & store the 2 output rows of this chunk.
        #pragma unroll
        for (int j = 0; j < 2; ++j) {
            float a0 = 0.f, a1 = 0.f, a2 = 0.f, a3 = 0.f;
            #pragma unroll
            for (int t = 0; t < 3; ++t) {
                const int i = j + t;
                const float k0 = k[t * 3 + 0];
                const float k1 = k[t * 3 + 1];
                const float k2 = k[t * 3 + 2];
                const float4 m = mid[cur][i];
                a0 = fmaf(lf[i], k0, fmaf(m.x, k1, fmaf(m.y,   k2, a0)));
                a1 = fmaf(m.x,   k0, fmaf(m.y, k1, fmaf(m.z,   k2, a1)));
                a2 = fmaf(m.y,   k0, fmaf(m.z, k1, fmaf(m.w,   k2, a2)));
                a3 = fmaf(m.z,   k0, fmaf(m.w, k1, fmaf(rt[i], k2, a3)));
            }
            const float4 xc = mid[cur][j + 1];
            const float4 fj = fv[cur][j];
            float4 o;
            o.x = xc.x + (fj.x - a0) * inv6;
            o.y = xc.y + (fj.y - a1) * inv6;
            o.z = xc.z + (fj.z - a2) * inv6;
            o.w = xc.w + (fj.w - a3) * inv6;
            *reinterpret_cast<float4*>(ob + (size_t)(r0 + 2*c + j) * IMG_W + c0) = o;
        }
    }
    #undef LOAD_CHUNK
}

extern "C" void kernel_launch(void* const* d_in, const int* in_sizes, int n_in,
                              void* d_out, int out_size)
{
    const float* x  = (const float*)d_in[0];   // [64,1,512,512]
    const float* f  = (const float*)d_in[1];   // [64,1,512,512]
    const float* kA = (const float*)d_in[2];   // [64,1,3,3]
    float* out = (float*)d_out;

    dim3 block(32, 4, 1);
    dim3 grid(IMG_W / (32 * 4), IMG_H / (4 * 8), 64); // (4, 16, 64)
    cheby_smooth_kernel<<<grid, block>>>(x, f, kA, out);
}